// round 1
// baseline (speedup 1.0000x reference)
#include <cuda_runtime.h>

#define BATCH 16384
#define NF 26
#define VOCAB 100000
#define ED 32
#define DIN 832          // NF*ED
#define H1 256
#define H2 128
#define BN_EPS 1e-5f

// ---------------- scratch (static device globals; no runtime alloc) ----------
__device__ float g_x[BATCH * DIN];     // gathered embeddings (54.5 MB)
__device__ float g_h1[BATCH * H1];     // layer-1 pre-BN activations
__device__ float g_h2[BATCH * H2];     // layer-2 pre-BN activations
__device__ float g_stats1[2 * H1];     // col sum / sumsq for h1
__device__ float g_stats2[2 * H2];
__device__ float g_scale1[H1], g_shift1[H1];
__device__ float g_scale2[H2], g_shift2[H2];

// ---------------- zero the atomic accumulators (needed per graph replay) -----
__global__ void k_zero_stats() {
    int t = threadIdx.x;
    if (t < 2 * H1) g_stats1[t] = 0.f;
    if (t < 2 * H2) g_stats2[t] = 0.f;
}

// ---------------- gather + FM logit ------------------------------------------
// One warp per sample row. Lane = embedding dim. Each of the 26 field rows is
// a 128B contiguous line -> fully coalesced gathers.
__global__ void k_gather_fm(const int* __restrict__ xc,
                            const float* __restrict__ lin,
                            const float* __restrict__ lat,
                            const float* __restrict__ bias,
                            float* __restrict__ out) {
    int warp = (blockIdx.x * blockDim.x + threadIdx.x) >> 5;
    int lane = threadIdx.x & 31;
    if (warp >= BATCH) return;
    int row = warp;

    int myidx = 0;
    float linv = 0.f;
    if (lane < NF) {
        myidx = xc[row * NF + lane];
        linv = lin[lane * VOCAB + myidx];
    }

    float s = 0.f, ss = 0.f;
#pragma unroll
    for (int f = 0; f < NF; f++) {
        int idx = __shfl_sync(0xffffffffu, myidx, f);
        float v = lat[(f * VOCAB + idx) * ED + lane];
        g_x[row * DIN + f * ED + lane] = v;
        s += v;
        ss += v * v;
    }
    float red = linv;      // linear part (lanes >= 26 contribute 0)
    float sq = s * s;      // per-dim (sum v)^2 ; reduce over lanes
#pragma unroll
    for (int o = 16; o; o >>= 1) {
        red += __shfl_xor_sync(0xffffffffu, red, o);
        sq  += __shfl_xor_sync(0xffffffffu, sq, o);
        ss  += __shfl_xor_sync(0xffffffffu, ss, o);
    }
    if (lane == 0) out[row] = red + 0.5f * (sq - ss) + bias[0];
}

// ---------------- fp32 SGEMM, 128x128x16 tiles, 8x8 per thread ---------------
// XFORM=false: C(g_h1) = g_x @ B + bias           (K=832, N=256)
// XFORM=true : C(g_h2) = relu(bn(g_h1)) @ B + bias (K=256, N=128)
template <int Kc, int Nc, bool XFORM>
__global__ __launch_bounds__(256, 2) void k_gemm(const float* __restrict__ B,
                                                 const float* __restrict__ bias) {
    constexpr int BM = 128, BN = 128, BK = 16;
    __shared__ float As[BK][BM];
    __shared__ float Bs[BK][BN];

    const float* __restrict__ A = XFORM ? g_h1 : g_x;
    float* __restrict__ C       = XFORM ? g_h2 : g_h1;
    const float* __restrict__ scale = g_scale1;
    const float* __restrict__ shift = g_shift1;

    int tid = threadIdx.x;
    int bm = blockIdx.y * BM;
    int bn = blockIdx.x * BN;
    int tx = tid & 15, ty = tid >> 4;

    float acc[8][8];
#pragma unroll
    for (int i = 0; i < 8; i++)
#pragma unroll
        for (int j = 0; j < 8; j++) acc[i][j] = 0.f;

    for (int k0 = 0; k0 < Kc; k0 += BK) {
        // A tile: 128 rows x 16 k, loaded as float4 along K, stored transposed
#pragma unroll
        for (int l = 0; l < 2; l++) {
            int slot = tid + l * 256;
            int row = slot >> 2, kq = slot & 3;
            float4 v = *(const float4*)(A + (size_t)(bm + row) * Kc + k0 + kq * 4);
            if (XFORM) {
                int kb = k0 + kq * 4;
                v.x = fmaxf(fmaf(v.x, scale[kb + 0], shift[kb + 0]), 0.f);
                v.y = fmaxf(fmaf(v.y, scale[kb + 1], shift[kb + 1]), 0.f);
                v.z = fmaxf(fmaf(v.z, scale[kb + 2], shift[kb + 2]), 0.f);
                v.w = fmaxf(fmaf(v.w, scale[kb + 3], shift[kb + 3]), 0.f);
            }
            As[kq * 4 + 0][row] = v.x;
            As[kq * 4 + 1][row] = v.y;
            As[kq * 4 + 2][row] = v.z;
            As[kq * 4 + 3][row] = v.w;
        }
        // B tile: 16 k-rows x 128 n
#pragma unroll
        for (int l = 0; l < 2; l++) {
            int slot = tid + l * 256;
            int kr = slot >> 5, nq = slot & 31;
            *(float4*)(&Bs[kr][nq * 4]) =
                *(const float4*)(B + (size_t)(k0 + kr) * Nc + bn + nq * 4);
        }
        __syncthreads();
#pragma unroll
        for (int kk = 0; kk < BK; kk++) {
            float ra[8], rb[8];
            *(float4*)(ra)     = *(const float4*)(&As[kk][ty * 8]);
            *(float4*)(ra + 4) = *(const float4*)(&As[kk][ty * 8 + 4]);
            *(float4*)(rb)     = *(const float4*)(&Bs[kk][tx * 8]);
            *(float4*)(rb + 4) = *(const float4*)(&Bs[kk][tx * 8 + 4]);
#pragma unroll
            for (int i = 0; i < 8; i++)
#pragma unroll
                for (int j = 0; j < 8; j++)
                    acc[i][j] = fmaf(ra[i], rb[j], acc[i][j]);
        }
        __syncthreads();
    }

#pragma unroll
    for (int i = 0; i < 8; i++) {
        int r = bm + ty * 8 + i;
#pragma unroll
        for (int j = 0; j < 8; j += 4) {
            int c = bn + tx * 8 + j;
            float4 v;
            v.x = acc[i][j + 0] + bias[c + 0];
            v.y = acc[i][j + 1] + bias[c + 1];
            v.z = acc[i][j + 2] + bias[c + 2];
            v.w = acc[i][j + 3] + bias[c + 3];
            *(float4*)(C + (size_t)r * Nc + c) = v;
        }
    }
}

// ---------------- column sum / sumsq (coalesced, thread = column) ------------
template <int COLS, int RPB>
__global__ void k_colstats() {
    const float* __restrict__ src = (COLS == H1) ? g_h1 : g_h2;
    float* __restrict__ stats     = (COLS == H1) ? g_stats1 : g_stats2;
    int t = threadIdx.x;
    size_t base = (size_t)blockIdx.x * RPB * COLS;
    float s = 0.f, sq = 0.f;
#pragma unroll 4
    for (int r = 0; r < RPB; r++) {
        float v = src[base + (size_t)r * COLS + t];
        s += v;
        sq += v * v;
    }
    atomicAdd(&stats[t], s);
    atomicAdd(&stats[COLS + t], sq);
}

// ---------------- finalize BN: scale = g*rsqrt(var+eps), shift = be - m*scale
template <int COLS>
__global__ void k_finalize(const float* __restrict__ g, const float* __restrict__ be) {
    const float* __restrict__ stats = (COLS == H1) ? g_stats1 : g_stats2;
    float* __restrict__ scale = (COLS == H1) ? g_scale1 : g_scale2;
    float* __restrict__ shift = (COLS == H1) ? g_shift1 : g_shift2;
    int t = threadIdx.x;
    const float inv = 1.f / (float)BATCH;
    float m = stats[t] * inv;
    float var = stats[COLS + t] * inv - m * m;
    float sc = g[t] * rsqrtf(var + BN_EPS);
    scale[t] = sc;
    shift[t] = be[t] - m * sc;
}

// ---------------- final layer: out += relu(bn(h2)) @ W3 + b3 -----------------
__global__ void k_final(const float* __restrict__ W3, const float* __restrict__ b3,
                        float* __restrict__ out) {
    int warp = (blockIdx.x * blockDim.x + threadIdx.x) >> 5;
    int lane = threadIdx.x & 31;
    if (warp >= BATCH) return;
    float acc = 0.f;
#pragma unroll
    for (int j0 = 0; j0 < H2; j0 += 32) {
        int j = j0 + lane;
        float v = g_h2[warp * H2 + j];
        float a = fmaxf(fmaf(v, g_scale2[j], g_shift2[j]), 0.f);
        acc = fmaf(a, W3[j], acc);
    }
#pragma unroll
    for (int o = 16; o; o >>= 1) acc += __shfl_xor_sync(0xffffffffu, acc, o);
    if (lane == 0) out[warp] += acc + b3[0];
}

// -----------------------------------------------------------------------------
extern "C" void kernel_launch(void* const* d_in, const int* in_sizes, int n_in,
                              void* d_out, int out_size) {
    const int*   xc   = (const int*)d_in[0];
    const float* lin  = (const float*)d_in[1];
    const float* lat  = (const float*)d_in[2];
    const float* W1   = (const float*)d_in[3];
    const float* b1   = (const float*)d_in[4];
    const float* g1   = (const float*)d_in[5];
    const float* be1  = (const float*)d_in[6];
    const float* W2   = (const float*)d_in[7];
    const float* b2   = (const float*)d_in[8];
    const float* g2   = (const float*)d_in[9];
    const float* be2  = (const float*)d_in[10];
    const float* W3   = (const float*)d_in[11];
    const float* b3   = (const float*)d_in[12];
    const float* bias = (const float*)d_in[13];
    float* out = (float*)d_out;

    k_zero_stats<<<1, 512>>>();
    k_gather_fm<<<BATCH / 8, 256>>>(xc, lin, lat, bias, out);
    k_gemm<DIN, H1, false><<<dim3(H1 / 128, BATCH / 128), 256>>>(W1, b1);
    k_colstats<H1, 256><<<BATCH / 256, H1>>>();
    k_finalize<H1><<<1, H1>>>(g1, be1);
    k_gemm<H1, H2, true><<<dim3(H2 / 128, BATCH / 128), 256>>>(W2, b2);
    k_colstats<H2, 128><<<BATCH / 128, H2>>>();
    k_finalize<H2><<<1, H2>>>(g2, be2);
    k_final<<<BATCH / 8, 256>>>(W3, b3, out);
}

// round 2
// speedup vs baseline: 1.1254x; 1.1254x over previous
#include <cuda_runtime.h>

#define BATCH 16384
#define NF 26
#define VOCAB 100000
#define ED 32
#define DIN 832          // NF*ED
#define H1 256
#define H2 128
#define BN_EPS 1e-5f

// ---------------- scratch ----------------------------------------------------
__device__ float g_h1[BATCH * H1];
__device__ float g_h2[BATCH * H2];
__device__ float g_stats1[2 * H1];
__device__ float g_stats2[2 * H2];
__device__ float g_scale1[H1], g_shift1[H1];
__device__ float g_scale2[H2], g_shift2[H2];

__global__ void k_zero_stats() {
    int t = threadIdx.x;
    if (t < 2 * H1) g_stats1[t] = 0.f;
    if (t < 2 * H2) g_stats2[t] = 0.f;
}

// =============================================================================
// Fused kernel 1: embedding gather + FM logit + GEMM1 (x @ W1 + b1) + col stats
// grid = 128 blocks (BM=128 rows each), 512 threads.
// BK = 32 = ED: one K-step per field; A-tile gathered straight from tables.
// Dynamic smem: sidx[128*26] | As[32][128] | Bs[32][256] (Bs reused for stats)
// =============================================================================
#define SM_IDX_B   (128 * NF * 4)          // 13312
#define SM_AS_B    (32 * 128 * 4)          // 16384
#define SM_BS_B    (32 * 256 * 4)          // 32768
#define SM_F1_TOT  (SM_IDX_B + SM_AS_B + SM_BS_B)

__global__ __launch_bounds__(512, 1) void k_fused1(
    const int* __restrict__ xc, const float* __restrict__ lin,
    const float* __restrict__ lat, const float* __restrict__ W1,
    const float* __restrict__ b1, const float* __restrict__ bias,
    float* __restrict__ out) {
    extern __shared__ char smem[];
    int*   sidx = (int*)smem;
    float* As   = (float*)(smem + SM_IDX_B);              // [32][128] k-major
    float* Bs   = (float*)(smem + SM_IDX_B + SM_AS_B);    // [32][256]
    float* red  = Bs;                                     // epilogue reuse

    const int tid = threadIdx.x;
    const int bm  = blockIdx.x * 128;

    // block's 128x26 indices
    for (int i = tid; i < 128 * NF; i += 512) sidx[i] = xc[bm * NF + i];
    __syncthreads();

    const int lrow = tid >> 2;        // gather mapping: 4 threads per row
    const int lq   = tid & 3;         // dims lq*8 .. lq*8+7
    const int tx   = tid & 31;        // compute mapping: cols tx*8..+8
    const int ty   = tid >> 5;        // rows ty*8..+8

    float acc[8][8];
#pragma unroll
    for (int i = 0; i < 8; i++)
#pragma unroll
        for (int j = 0; j < 8; j++) acc[i][j] = 0.f;

    float s[8];                       // FM per-dim sums for (lrow, lq-dims)
#pragma unroll
    for (int j = 0; j < 8; j++) s[j] = 0.f;
    float ss = 0.f;                   // FM sum of squares

    float pa[8], pb[16];
    // prefetch field 0
    {
        size_t idx = (size_t)sidx[lrow * NF];
        const float* src = lat + idx * ED + lq * 8;
        *(float4*)(pa)     = *(const float4*)(src);
        *(float4*)(pa + 4) = *(const float4*)(src + 4);
#pragma unroll
        for (int l = 0; l < 4; l++) {
            int slot = tid + l * 512;
            *(float4*)(pb + l * 4) =
                *(const float4*)(W1 + (size_t)(slot >> 6) * H1 + (slot & 63) * 4);
        }
    }

    for (int f = 0; f < NF; f++) {
        // stage prefetched tile to smem; fold FM accumulation
#pragma unroll
        for (int j = 0; j < 8; j++) {
            As[(lq * 8 + j) * 128 + lrow] = pa[j];
            s[j] += pa[j];
            ss = fmaf(pa[j], pa[j], ss);
        }
#pragma unroll
        for (int l = 0; l < 4; l++) {
            int slot = tid + l * 512;
            *(float4*)(&Bs[(slot >> 6) * 256 + (slot & 63) * 4]) = *(const float4*)(pb + l * 4);
        }
        __syncthreads();

        // prefetch next field while FMAs run
        if (f + 1 < NF) {
            size_t idx = (size_t)(f + 1) * VOCAB + sidx[lrow * NF + f + 1];
            const float* src = lat + idx * ED + lq * 8;
            *(float4*)(pa)     = *(const float4*)(src);
            *(float4*)(pa + 4) = *(const float4*)(src + 4);
#pragma unroll
            for (int l = 0; l < 4; l++) {
                int slot = tid + l * 512;
                *(float4*)(pb + l * 4) = *(const float4*)(
                    W1 + (size_t)((f + 1) * 32 + (slot >> 6)) * H1 + (slot & 63) * 4);
            }
        }

#pragma unroll
        for (int kk = 0; kk < 32; kk++) {
            float ra[8], rb[8];
            *(float4*)(ra)     = *(const float4*)(&As[kk * 128 + ty * 8]);
            *(float4*)(ra + 4) = *(const float4*)(&As[kk * 128 + ty * 8 + 4]);
            *(float4*)(rb)     = *(const float4*)(&Bs[kk * 256 + tx * 8]);
            *(float4*)(rb + 4) = *(const float4*)(&Bs[kk * 256 + tx * 8 + 4]);
#pragma unroll
            for (int i = 0; i < 8; i++)
#pragma unroll
                for (int j = 0; j < 8; j++) acc[i][j] = fmaf(ra[i], rb[j], acc[i][j]);
        }
        __syncthreads();
    }

    // ---------------- FM logit (per-row, via 4-lane groups) ------------------
    {
        float sq = 0.f;
#pragma unroll
        for (int j = 0; j < 8; j++) sq = fmaf(s[j], s[j], sq);
        float lv = 0.f;
        for (int f = lq; f < NF; f += 4)
            lv += lin[(size_t)f * VOCAB + sidx[lrow * NF + f]];
        sq += __shfl_xor_sync(0xffffffffu, sq, 1);
        sq += __shfl_xor_sync(0xffffffffu, sq, 2);
        ss += __shfl_xor_sync(0xffffffffu, ss, 1);
        ss += __shfl_xor_sync(0xffffffffu, ss, 2);
        lv += __shfl_xor_sync(0xffffffffu, lv, 1);
        lv += __shfl_xor_sync(0xffffffffu, lv, 2);
        if (lq == 0) out[bm + lrow] = lv + 0.5f * (sq - ss) + bias[0];
    }

    // ---------------- epilogue: write h1, accumulate column stats ------------
    float bc[8];
    *(float4*)(bc)     = *(const float4*)(b1 + tx * 8);
    *(float4*)(bc + 4) = *(const float4*)(b1 + tx * 8 + 4);
    float csum[8], csq[8];
#pragma unroll
    for (int j = 0; j < 8; j++) { csum[j] = 0.f; csq[j] = 0.f; }
#pragma unroll
    for (int i = 0; i < 8; i++) {
        int r = bm + ty * 8 + i;
        float h[8];
#pragma unroll
        for (int j = 0; j < 8; j++) {
            h[j] = acc[i][j] + bc[j];
            csum[j] += h[j];
            csq[j] = fmaf(h[j], h[j], csq[j]);
        }
        *(float4*)(g_h1 + (size_t)r * H1 + tx * 8)     = *(float4*)(h);
        *(float4*)(g_h1 + (size_t)r * H1 + tx * 8 + 4) = *(float4*)(h + 4);
    }
    // reduce across the 16 ty-groups via smem (reuses Bs)
#pragma unroll
    for (int j = 0; j < 8; j++) red[ty * 256 + tx * 8 + j] = csum[j];
    __syncthreads();
    if (tid < 256) {
        float v = 0.f;
#pragma unroll
        for (int y = 0; y < 16; y++) v += red[y * 256 + tid];
        atomicAdd(&g_stats1[tid], v);
    }
    __syncthreads();
#pragma unroll
    for (int j = 0; j < 8; j++) red[ty * 256 + tx * 8 + j] = csq[j];
    __syncthreads();
    if (tid < 256) {
        float v = 0.f;
#pragma unroll
        for (int y = 0; y < 16; y++) v += red[y * 256 + tid];
        atomicAdd(&g_stats1[H1 + tid], v);
    }
}

// ---------------- finalize BN: scale = g*rsqrt(var+eps), shift = be - m*scale
template <int COLS>
__global__ void k_finalize(const float* __restrict__ g, const float* __restrict__ be) {
    const float* __restrict__ stats = (COLS == H1) ? g_stats1 : g_stats2;
    float* __restrict__ scale = (COLS == H1) ? g_scale1 : g_scale2;
    float* __restrict__ shift = (COLS == H1) ? g_shift1 : g_shift2;
    int t = threadIdx.x;
    const float inv = 1.f / (float)BATCH;
    float m = stats[t] * inv;
    float var = stats[COLS + t] * inv - m * m;
    float sc = g[t] * rsqrtf(var + BN_EPS);
    scale[t] = sc;
    shift[t] = be[t] - m * sc;
}

// =============================================================================
// GEMM2: h2 = relu(bn(h1)) @ W2 + b2, with fused column stats for h2.
// grid = 128 (BM=128, BN=128=H2 full), 256 threads, BK=16.
// =============================================================================
__global__ __launch_bounds__(256, 2) void k_gemm2(const float* __restrict__ W2,
                                                  const float* __restrict__ b2) {
    __shared__ float As[16][128];
    __shared__ float Bs[16][128];

    int tid = threadIdx.x;
    int bm = blockIdx.x * 128;
    int tx = tid & 15, ty = tid >> 4;

    float acc[8][8];
#pragma unroll
    for (int i = 0; i < 8; i++)
#pragma unroll
        for (int j = 0; j < 8; j++) acc[i][j] = 0.f;

    for (int k0 = 0; k0 < H1; k0 += 16) {
#pragma unroll
        for (int l = 0; l < 2; l++) {
            int slot = tid + l * 256;
            int row = slot >> 2, kq = slot & 3;
            int kb = k0 + kq * 4;
            float4 v = *(const float4*)(g_h1 + (size_t)(bm + row) * H1 + kb);
            v.x = fmaxf(fmaf(v.x, g_scale1[kb + 0], g_shift1[kb + 0]), 0.f);
            v.y = fmaxf(fmaf(v.y, g_scale1[kb + 1], g_shift1[kb + 1]), 0.f);
            v.z = fmaxf(fmaf(v.z, g_scale1[kb + 2], g_shift1[kb + 2]), 0.f);
            v.w = fmaxf(fmaf(v.w, g_scale1[kb + 3], g_shift1[kb + 3]), 0.f);
            As[kq * 4 + 0][row] = v.x;
            As[kq * 4 + 1][row] = v.y;
            As[kq * 4 + 2][row] = v.z;
            As[kq * 4 + 3][row] = v.w;
        }
        {
            int kr = tid >> 5, nq = tid & 31;
            *(float4*)(&Bs[kr][nq * 4]) =
                *(const float4*)(W2 + (size_t)(k0 + kr) * H2 + nq * 4);
            int kr2 = kr + 8;
            *(float4*)(&Bs[kr2][nq * 4]) =
                *(const float4*)(W2 + (size_t)(k0 + kr2) * H2 + nq * 4);
        }
        __syncthreads();
#pragma unroll
        for (int kk = 0; kk < 16; kk++) {
            float ra[8], rb[8];
            *(float4*)(ra)     = *(const float4*)(&As[kk][ty * 8]);
            *(float4*)(ra + 4) = *(const float4*)(&As[kk][ty * 8 + 4]);
            *(float4*)(rb)     = *(const float4*)(&Bs[kk][tx * 8]);
            *(float4*)(rb + 4) = *(const float4*)(&Bs[kk][tx * 8 + 4]);
#pragma unroll
            for (int i = 0; i < 8; i++)
#pragma unroll
                for (int j = 0; j < 8; j++) acc[i][j] = fmaf(ra[i], rb[j], acc[i][j]);
        }
        __syncthreads();
    }

    // epilogue: write h2 + column stats
    float bc[8];
    *(float4*)(bc)     = *(const float4*)(b2 + tx * 8);
    *(float4*)(bc + 4) = *(const float4*)(b2 + tx * 8 + 4);
    float csum[8], csq[8];
#pragma unroll
    for (int j = 0; j < 8; j++) { csum[j] = 0.f; csq[j] = 0.f; }
#pragma unroll
    for (int i = 0; i < 8; i++) {
        int r = bm + ty * 8 + i;
        float h[8];
#pragma unroll
        for (int j = 0; j < 8; j++) {
            h[j] = acc[i][j] + bc[j];
            csum[j] += h[j];
            csq[j] = fmaf(h[j], h[j], csq[j]);
        }
        *(float4*)(g_h2 + (size_t)r * H2 + tx * 8)     = *(float4*)(h);
        *(float4*)(g_h2 + (size_t)r * H2 + tx * 8 + 4) = *(float4*)(h + 4);
    }
    float* red = &As[0][0];   // 16*128 floats, exactly one plane
#pragma unroll
    for (int j = 0; j < 8; j++) red[ty * 128 + tx * 8 + j] = csum[j];
    __syncthreads();
    if (tid < 128) {
        float v = 0.f;
#pragma unroll
        for (int y = 0; y < 16; y++) v += red[y * 128 + tid];
        atomicAdd(&g_stats2[tid], v);
    }
    __syncthreads();
#pragma unroll
    for (int j = 0; j < 8; j++) red[ty * 128 + tx * 8 + j] = csq[j];
    __syncthreads();
    if (tid < 128) {
        float v = 0.f;
#pragma unroll
        for (int y = 0; y < 16; y++) v += red[y * 128 + tid];
        atomicAdd(&g_stats2[H2 + tid], v);
    }
}

// ---------------- final layer: out += relu(bn(h2)) @ W3 + b3 -----------------
__global__ void k_final(const float* __restrict__ W3, const float* __restrict__ b3,
                        float* __restrict__ out) {
    int warp = (blockIdx.x * blockDim.x + threadIdx.x) >> 5;
    int lane = threadIdx.x & 31;
    if (warp >= BATCH) return;
    float acc = 0.f;
#pragma unroll
    for (int j0 = 0; j0 < H2; j0 += 32) {
        int j = j0 + lane;
        float v = g_h2[(size_t)warp * H2 + j];
        float a = fmaxf(fmaf(v, g_scale2[j], g_shift2[j]), 0.f);
        acc = fmaf(a, W3[j], acc);
    }
#pragma unroll
    for (int o = 16; o; o >>= 1) acc += __shfl_xor_sync(0xffffffffu, acc, o);
    if (lane == 0) out[warp] += acc + b3[0];
}

// -----------------------------------------------------------------------------
extern "C" void kernel_launch(void* const* d_in, const int* in_sizes, int n_in,
                              void* d_out, int out_size) {
    const int*   xc   = (const int*)d_in[0];
    const float* lin  = (const float*)d_in[1];
    const float* lat  = (const float*)d_in[2];
    const float* W1   = (const float*)d_in[3];
    const float* b1   = (const float*)d_in[4];
    const float* g1   = (const float*)d_in[5];
    const float* be1  = (const float*)d_in[6];
    const float* W2   = (const float*)d_in[7];
    const float* b2   = (const float*)d_in[8];
    const float* g2   = (const float*)d_in[9];
    const float* be2  = (const float*)d_in[10];
    const float* W3   = (const float*)d_in[11];
    const float* b3   = (const float*)d_in[12];
    const float* bias = (const float*)d_in[13];
    float* out = (float*)d_out;

    cudaFuncSetAttribute(k_fused1, cudaFuncAttributeMaxDynamicSharedMemorySize,
                         SM_F1_TOT);

    k_zero_stats<<<1, 512>>>();
    k_fused1<<<BATCH / 128, 512, SM_F1_TOT>>>(xc, lin, lat, W1, b1, bias, out);
    k_finalize<H1><<<1, H1>>>(g1, be1);
    k_gemm2<<<BATCH / 128, 256>>>(W2, b2);
    k_finalize<H2><<<1, H2>>>(g2, be2);
    k_final<<<BATCH / 8, 256>>>(W3, b3, out);
}

// round 5
// speedup vs baseline: 1.4008x; 1.2447x over previous
#include <cuda_runtime.h>
#include <cuda_bf16.h>
#include <cstdint>

#define BATCH 16384
#define NF 26
#define VOCAB 100000
#define ED 32
#define DIN 832
#define H1 256
#define H2 128
#define BN_EPS 1e-5f

#define NCHUNK 13        // 13 chunks x (2 fields = 64 k-cols bf16)
#define KSTEPS 52        // 832 / 16
#define NT1 32           // 256 / 8 n-tiles

// ---------------- scratch ----------------------------------------------------
__device__ float g_h1[BATCH * H1];
__device__ float g_h2[BATCH * H2];
__device__ float g_stats1[2 * H1];
__device__ float g_stats2[2 * H2];
__device__ float g_scale1[H1], g_shift1[H1];
__device__ float g_scale2[H2], g_shift2[H2];
// W1 packed as HMMA B-fragments: [kstep][ntile][lane] -> uint2{b0,b1}
__device__ __align__(16) uint2 g_w1f_hi[KSTEPS * NT1 * 32];
__device__ __align__(16) uint2 g_w1f_lo[KSTEPS * NT1 * 32];

__device__ __forceinline__ uint32_t smem_u32(const void* p) {
    uint32_t a;
    asm("{ .reg .u64 t; cvta.to.shared.u64 t, %1; cvt.u32.u64 %0, t; }" : "=r"(a) : "l"(p));
    return a;
}

__device__ __forceinline__ void split2(float x, float y, uint32_t& hi, uint32_t& lo) {
    __nv_bfloat162 h;
    h.x = __float2bfloat16_rn(x);
    h.y = __float2bfloat16_rn(y);
    __nv_bfloat162 l;
    l.x = __float2bfloat16_rn(x - __bfloat162float(h.x));
    l.y = __float2bfloat16_rn(y - __bfloat162float(h.y));
    hi = *(uint32_t*)&h;
    lo = *(uint32_t*)&l;
}

#define LDSM_X4(r, addr)                                                       \
    asm volatile("ldmatrix.sync.aligned.m8n8.x4.shared.b16 {%0,%1,%2,%3}, [%4];" \
                 : "=r"((r)[0]), "=r"((r)[1]), "=r"((r)[2]), "=r"((r)[3])      \
                 : "r"(addr))

#define MMA_BF16(d, a, b0, b1)                                                 \
    asm volatile(                                                              \
        "mma.sync.aligned.m16n8k16.row.col.f32.bf16.bf16.f32 "                 \
        "{%0,%1,%2,%3},{%4,%5,%6,%7},{%8,%9},{%0,%1,%2,%3};"                   \
        : "+f"((d)[0]), "+f"((d)[1]), "+f"((d)[2]), "+f"((d)[3])               \
        : "r"((a)[0]), "r"((a)[1]), "r"((a)[2]), "r"((a)[3]), "r"(b0), "r"(b1))

__global__ void k_zero_stats() {
    int t = threadIdx.x;
    if (t < 2 * H1) g_stats1[t] = 0.f;
    if (t < 2 * H2) g_stats2[t] = 0.f;
}

// ---------------- W1 -> bf16 hi/lo HMMA B-fragment packing -------------------
// B frag (m16n8k16, col n = lane/4): b0 = {B[k0][n], B[k0+1][n]}, k0=(lane%4)*2
//                                    b1 = {B[k0+8][n], B[k0+9][n]}
__global__ void k_prep_w1(const float* __restrict__ W1) {
    int g = blockIdx.x * blockDim.x + threadIdx.x;
    if (g >= KSTEPS * NT1 * 32) return;
    int lane = g & 31, nt = (g >> 5) & 31, ks = g >> 10;
    int k0 = ks * 16 + (lane & 3) * 2;
    int n = nt * 8 + (lane >> 2);
    float v00 = W1[(size_t)(k0 + 0) * H1 + n];
    float v01 = W1[(size_t)(k0 + 1) * H1 + n];
    float v10 = W1[(size_t)(k0 + 8) * H1 + n];
    float v11 = W1[(size_t)(k0 + 9) * H1 + n];
    uint2 hi, lo;
    split2(v00, v01, hi.x, lo.x);
    split2(v10, v11, hi.y, lo.y);
    g_w1f_hi[g] = hi;
    g_w1f_lo[g] = lo;
}

// =============================================================================
// Fused: gather + FM + HMMA GEMM1 (bf16 split-3) + bias + column stats
// grid = 128 (BM=128), 256 threads (8 warps x 16 rows, N=256 full).
// =============================================================================
#define SM_SIDX  0                    // 128*26*4 = 13312
#define SM_SFM   13312                // 256 threads * 32 floats = 32768
#define SM_SSQ   46080                // 256 floats = 1024
#define SM_STAGE 47104                // Ahi 16384 + Alo 16384
#define SM_TOT   79872

__global__ __launch_bounds__(256, 1) void k_fused1(
    const int* __restrict__ xc, const float* __restrict__ lin,
    const float* __restrict__ lat, const float* __restrict__ b1,
    const float* __restrict__ bias, float* __restrict__ out) {
    extern __shared__ char smem[];
    int* sidx = (int*)(smem + SM_SIDX);
    float* sfm = (float*)(smem + SM_SFM);
    float* ssqb = (float*)(smem + SM_SSQ);
    char* Ahi = smem + SM_STAGE;
    char* Alo = smem + SM_STAGE + 16384;

    const int tid = threadIdx.x;
    const int bm = blockIdx.x * 128;
    const uint32_t sb = smem_u32(smem);

    for (int i = tid; i < 128 * NF; i += 256) sidx[i] = xc[bm * NF + i];

    const int row = tid & 127, fpar = tid >> 7;   // gather mapping
    const int w = tid >> 5, lane = tid & 31;      // mma mapping
    // ldmatrix x4 lane addressing: m0=rows0-7/q+0, m1=rows8-15/q+0, m2=rows0-7/q+1, m3=rows8-15/q+1
    const int g4 = lane >> 3;
    const int lr = w * 16 + (g4 & 1) * 8 + (lane & 7);
    const int qoff = g4 >> 1;

    float acc[NT1][4];
#pragma unroll
    for (int nt = 0; nt < NT1; nt++)
#pragma unroll
        for (int j = 0; j < 4; j++) acc[nt][j] = 0.f;
    float ssq = 0.f;

    __syncthreads();

    for (int c = 0; c < NCHUNK; c++) {
        // ---- gather one field-row (32 fp32), FM, split, store swizzled -----
        {
            const int field = 2 * c + fpar;
            const size_t erow = (size_t)field * VOCAB + sidx[row * NF + field];
            const float4* src = (const float4*)(lat + erow * ED);
            float4 f[8];
#pragma unroll
            for (int j = 0; j < 8; j++) f[j] = __ldg(src + j);
            const float* ff = (const float*)f;
#pragma unroll
            for (int j = 0; j < 32; j++) ssq = fmaf(ff[j], ff[j], ssq);
            float4* sf4 = (float4*)sfm + tid * 8;
            if (c == 0) {
#pragma unroll
                for (int j = 0; j < 8; j++) sf4[j] = f[j];
            } else {
#pragma unroll
                for (int j = 0; j < 8; j++) {
                    float4 t = sf4[j];
                    t.x += f[j].x; t.y += f[j].y; t.z += f[j].z; t.w += f[j].w;
                    sf4[j] = t;
                }
            }
#pragma unroll
            for (int j2 = 0; j2 < 4; j2++) {
                float4 a = f[2 * j2], b = f[2 * j2 + 1];
                uint4 hq, lq;
                split2(a.x, a.y, hq.x, lq.x);
                split2(a.z, a.w, hq.y, lq.y);
                split2(b.x, b.y, hq.z, lq.z);
                split2(b.z, b.w, hq.w, lq.w);
                int q = fpar * 4 + j2;
                uint32_t off = (uint32_t)row * 128 + ((q ^ (row & 7)) << 4);
                *(uint4*)(Ahi + off) = hq;
                *(uint4*)(Alo + off) = lq;
            }
        }
        __syncthreads();

        // ---- MMA: 4 k-steps of 16 over this chunk ---------------------------
#pragma unroll
        for (int ks = 0; ks < 4; ks++) {
            uint32_t ah[4], al[4];
            int q = ks * 2 + qoff;
            uint32_t addr = sb + SM_STAGE + (uint32_t)lr * 128 + ((q ^ (lr & 7)) << 4);
            LDSM_X4(ah, addr);
            LDSM_X4(al, addr + 16384);
            const uint2* bh = g_w1f_hi + (size_t)(c * 4 + ks) * (NT1 * 32) + lane;
            const uint2* bl = g_w1f_lo + (size_t)(c * 4 + ks) * (NT1 * 32) + lane;
#pragma unroll
            for (int nt = 0; nt < NT1; nt++) {
                uint2 B0 = __ldg(bh + nt * 32);
                uint2 B1 = __ldg(bl + nt * 32);
                MMA_BF16(acc[nt], ah, B0.x, B0.y);
                MMA_BF16(acc[nt], ah, B1.x, B1.y);
                MMA_BF16(acc[nt], al, B0.x, B0.y);
            }
        }
        __syncthreads();
    }

    // ---- FM logit -----------------------------------------------------------
    ssqb[tid] = ssq;
    __syncthreads();
    if (tid < 128) {
        const float4* sf4 = (const float4*)sfm;
        float sq = 0.f;
#pragma unroll
        for (int j = 0; j < 8; j++) {
            float4 u = sf4[tid * 8 + j];
            float4 v = sf4[(128 + tid) * 8 + j];
            float s0 = u.x + v.x, s1 = u.y + v.y, s2 = u.z + v.z, s3 = u.w + v.w;
            sq = fmaf(s0, s0, sq); sq = fmaf(s1, s1, sq);
            sq = fmaf(s2, s2, sq); sq = fmaf(s3, s3, sq);
        }
        float st = ssqb[tid] + ssqb[128 + tid];
        float lv = 0.f;
        for (int f = 0; f < NF; f++)
            lv += __ldg(lin + (size_t)f * VOCAB + sidx[tid * NF + f]);
        out[bm + tid] = lv + 0.5f * (sq - st) + bias[0];
    }

    // ---- epilogue: write h1 + column stats (stats smem reuses stage) --------
    float* ss = (float*)(smem + SM_STAGE);       // 256 col sums
    float* qs = ss + 256;                        // 256 col sumsq
    ss[tid] = 0.f;
    qs[tid] = 0.f;
    __syncthreads();

    const int ra = bm + w * 16 + (lane >> 2);
    const int cb = (lane & 3) * 2;
#pragma unroll
    for (int nt = 0; nt < NT1; nt++) {
        int cc = nt * 8 + cb;
        float2 bb = *(const float2*)(b1 + cc);
        float h0 = acc[nt][0] + bb.x, h1 = acc[nt][1] + bb.y;
        float h2 = acc[nt][2] + bb.x, h3 = acc[nt][3] + bb.y;
        float2 r0v = make_float2(h0, h1), r1v = make_float2(h2, h3);
        *(float2*)(g_h1 + (size_t)ra * H1 + cc) = r0v;
        *(float2*)(g_h1 + (size_t)(ra + 8) * H1 + cc) = r1v;
        float s0 = h0 + h2, s1 = h1 + h3;
        float q0 = h0 * h0 + h2 * h2, q1 = h1 * h1 + h3 * h3;
#pragma unroll
        for (int o = 4; o <= 16; o <<= 1) {
            s0 += __shfl_xor_sync(0xffffffffu, s0, o);
            s1 += __shfl_xor_sync(0xffffffffu, s1, o);
            q0 += __shfl_xor_sync(0xffffffffu, q0, o);
            q1 += __shfl_xor_sync(0xffffffffu, q1, o);
        }
        if ((lane >> 2) == 0) {
            atomicAdd(&ss[cc], s0);
            atomicAdd(&ss[cc + 1], s1);
            atomicAdd(&qs[cc], q0);
            atomicAdd(&qs[cc + 1], q1);
        }
    }
    __syncthreads();
    atomicAdd(&g_stats1[tid], ss[tid]);
    atomicAdd(&g_stats1[H1 + tid], qs[tid]);
}

// ---------------- finalize BN ------------------------------------------------
template <int COLS>
__global__ void k_finalize(const float* __restrict__ g, const float* __restrict__ be) {
    const float* __restrict__ stats = (COLS == H1) ? g_stats1 : g_stats2;
    float* __restrict__ scale = (COLS == H1) ? g_scale1 : g_scale2;
    float* __restrict__ shift = (COLS == H1) ? g_shift1 : g_shift2;
    int t = threadIdx.x;
    const float inv = 1.f / (float)BATCH;
    float m = stats[t] * inv;
    float var = stats[COLS + t] * inv - m * m;
    float sc = g[t] * rsqrtf(var + BN_EPS);
    scale[t] = sc;
    shift[t] = be[t] - m * sc;
}

// =============================================================================
// GEMM2: h2 = relu(bn(h1)) @ W2 + b2 (+ column stats). BM=64, grid=256.
// =============================================================================
__global__ __launch_bounds__(256, 3) void k_gemm2(const float* __restrict__ W2,
                                                  const float* __restrict__ b2) {
    __shared__ float sm[16 * 64 + 16 * 128];
    float* As = sm;
    float* Bs = sm + 16 * 64;

    int tid = threadIdx.x;
    int bm = blockIdx.x * 64;
    int tx = tid & 15, ty = tid >> 4;

    float acc[4][8];
#pragma unroll
    for (int i = 0; i < 4; i++)
#pragma unroll
        for (int j = 0; j < 8; j++) acc[i][j] = 0.f;

    for (int k0 = 0; k0 < H1; k0 += 16) {
        {
            int rrow = tid >> 2, kq = tid & 3;
            int kb = k0 + kq * 4;
            float4 v = *(const float4*)(g_h1 + (size_t)(bm + rrow) * H1 + kb);
            v.x = fmaxf(fmaf(v.x, g_scale1[kb + 0], g_shift1[kb + 0]), 0.f);
            v.y = fmaxf(fmaf(v.y, g_scale1[kb + 1], g_shift1[kb + 1]), 0.f);
            v.z = fmaxf(fmaf(v.z, g_scale1[kb + 2], g_shift1[kb + 2]), 0.f);
            v.w = fmaxf(fmaf(v.w, g_scale1[kb + 3], g_shift1[kb + 3]), 0.f);
            As[(kq * 4 + 0) * 64 + rrow] = v.x;
            As[(kq * 4 + 1) * 64 + rrow] = v.y;
            As[(kq * 4 + 2) * 64 + rrow] = v.z;
            As[(kq * 4 + 3) * 64 + rrow] = v.w;
        }
#pragma unroll
        for (int l = 0; l < 2; l++) {
            int slot = tid + l * 256;
            int kr = slot >> 5, nq = slot & 31;
            *(float4*)(&Bs[kr * 128 + nq * 4]) =
                *(const float4*)(W2 + (size_t)(k0 + kr) * H2 + nq * 4);
        }
        __syncthreads();
#pragma unroll
        for (int kk = 0; kk < 16; kk++) {
            float ra[4], rb[8];
            *(float4*)(ra)     = *(const float4*)(&As[kk * 64 + ty * 4]);
            *(float4*)(rb)     = *(const float4*)(&Bs[kk * 128 + tx * 8]);
            *(float4*)(rb + 4) = *(const float4*)(&Bs[kk * 128 + tx * 8 + 4]);
#pragma unroll
            for (int i = 0; i < 4; i++)
#pragma unroll
                for (int j = 0; j < 8; j++) acc[i][j] = fmaf(ra[i], rb[j], acc[i][j]);
        }
        __syncthreads();
    }

    float bc[8];
    *(float4*)(bc)     = *(const float4*)(b2 + tx * 8);
    *(float4*)(bc + 4) = *(const float4*)(b2 + tx * 8 + 4);
    float csum[8], csq[8];
#pragma unroll
    for (int j = 0; j < 8; j++) { csum[j] = 0.f; csq[j] = 0.f; }
#pragma unroll
    for (int i = 0; i < 4; i++) {
        int r = bm + ty * 4 + i;
        float hh[8];
#pragma unroll
        for (int j = 0; j < 8; j++) {
            hh[j] = acc[i][j] + bc[j];
            csum[j] += hh[j];
            csq[j] = fmaf(hh[j], hh[j], csq[j]);
        }
        *(float4*)(g_h2 + (size_t)r * H2 + tx * 8)     = *(float4*)(hh);
        *(float4*)(g_h2 + (size_t)r * H2 + tx * 8 + 4) = *(float4*)(hh + 4);
    }
    float* red = sm;
#pragma unroll
    for (int j = 0; j < 8; j++) red[ty * 128 + tx * 8 + j] = csum[j];
    __syncthreads();
    if (tid < 128) {
        float v = 0.f;
#pragma unroll
        for (int y = 0; y < 16; y++) v += red[y * 128 + tid];
        atomicAdd(&g_stats2[tid], v);
    }
    __syncthreads();
#pragma unroll
    for (int j = 0; j < 8; j++) red[ty * 128 + tx * 8 + j] = csq[j];
    __syncthreads();
    if (tid < 128) {
        float v = 0.f;
#pragma unroll
        for (int y = 0; y < 16; y++) v += red[y * 128 + tid];
        atomicAdd(&g_stats2[H2 + tid], v);
    }
}

// ---------------- final layer ------------------------------------------------
__global__ void k_final(const float* __restrict__ W3, const float* __restrict__ b3,
                        float* __restrict__ out) {
    int warp = (blockIdx.x * blockDim.x + threadIdx.x) >> 5;
    int lane = threadIdx.x & 31;
    if (warp >= BATCH) return;
    float acc = 0.f;
#pragma unroll
    for (int j0 = 0; j0 < H2; j0 += 32) {
        int j = j0 + lane;
        float v = g_h2[(size_t)warp * H2 + j];
        float a = fmaxf(fmaf(v, g_scale2[j], g_shift2[j]), 0.f);
        acc = fmaf(a, W3[j], acc);
    }
#pragma unroll
    for (int o = 16; o; o >>= 1) acc += __shfl_xor_sync(0xffffffffu, acc, o);
    if (lane == 0) out[warp] += acc + b3[0];
}

// -----------------------------------------------------------------------------
extern "C" void kernel_launch(void* const* d_in, const int* in_sizes, int n_in,
                              void* d_out, int out_size) {
    const int*   xc   = (const int*)d_in[0];
    const float* lin  = (const float*)d_in[1];
    const float* lat  = (const float*)d_in[2];
    const float* W1   = (const float*)d_in[3];
    const float* b1   = (const float*)d_in[4];
    const float* g1   = (const float*)d_in[5];
    const float* be1  = (const float*)d_in[6];
    const float* W2   = (const float*)d_in[7];
    const float* b2   = (const float*)d_in[8];
    const float* g2   = (const float*)d_in[9];
    const float* be2  = (const float*)d_in[10];
    const float* W3   = (const float*)d_in[11];
    const float* b3   = (const float*)d_in[12];
    const float* bias = (const float*)d_in[13];
    float* out = (float*)d_out;

    cudaFuncSetAttribute(k_fused1, cudaFuncAttributeMaxDynamicSharedMemorySize,
                         SM_TOT);

    k_prep_w1<<<(KSTEPS * NT1 * 32 + 255) / 256, 256>>>(W1);
    k_zero_stats<<<1, 512>>>();
    k_fused1<<<BATCH / 128, 256, SM_TOT>>>(xc, lin, lat, b1, bias, out);
    k_finalize<H1><<<1, H1>>>(g1, be1);
    k_gemm2<<<BATCH / 64, 256>>>(W2, b2);
    k_finalize<H2><<<1, H2>>>(g2, be2);
    k_final<<<BATCH / 8, 256>>>(W3, b3, out);
}